// round 3
// baseline (speedup 1.0000x reference)
#include <cuda_runtime.h>

#define NBATCH 256
#define TLEN   256
#define DZ     32
#define DA     16
#define DU     8
#define KMIX   4
#define HID    64
#define G3     192   // 3*HID
#define SPAD   36    // row pad: float4-aligned, decent bank spread

// output segment offsets (floats, all < 2^31); order: z, mu, Sig, a, A_t, B_t, C_t
#define OFF_Z   0u
#define OFF_MU  2097152u
#define OFF_SIG 4194304u
#define OFF_A   71303168u
#define OFF_AT  72351744u
#define OFF_BT  139460608u
#define OFF_CT  156237824u

struct Smem {
    float A[DZ][SPAD];   // A_t
    float L[DZ][SPAD];   // cholesky factor (lower, upper zeroed)
    float G[DZ][SPAD];   // A_t @ L
    float S[DZ][SPAD];   // Sigma_t
    float Q[DZ][SPAD];
    float Ct[DA][SPAD];
    float Bt[DZ][DU];
    float mu[DZ];
    float mun[DZ];
    float h[HID];
    float z[DZ];
    float eps[DZ];
    float u[DU];
    float gh[G3];
    float gx[G3];
    float alpha[KMIX];
};

// Warp 0 (lane = row): in-register Cholesky of sm.S -> sm.L,
// fused z = mu_next + L @ eps accumulated column-by-column.
__device__ __forceinline__ void chol32_warp(Smem& sm, int lane)
{
    float a[DZ];
#pragma unroll
    for (int k = 0; k < DZ; ++k) a[k] = sm.S[lane][k];
    float eps_own = sm.eps[lane];
    float zacc    = sm.mun[lane];
#pragma unroll
    for (int j = 0; j < DZ; ++j) {
        float d   = __shfl_sync(0xffffffffu, a[j], j);   // current diagonal
        float rs  = rsqrtf(d);
        float lij = a[j] * rs;                            // L[lane][j] (valid for lane>=j)
        a[j] = lij;
        float ej = __shfl_sync(0xffffffffu, eps_own, j);
        if (lane >= j) zacc = fmaf(lij, ej, zacc);        // z accum off the d-chain
        float lsq = lij * lij;
#pragma unroll
        for (int k = j + 1; k < DZ; ++k) {
            float lkj = __shfl_sync(0xffffffffu, lij, k); // L[k][j] from lane k
            if (k == lane) a[k] -= lsq;                   // own diag: no shfl dep
            else           a[k] = fmaf(-lij, lkj, a[k]);
        }
    }
#pragma unroll
    for (int k = 0; k < DZ; ++k) sm.L[lane][k] = (k <= lane) ? a[k] : 0.f;
    sm.z[lane] = zacc;
}

__global__ void __launch_bounds__(256, 2)
lgssm_kernel(const float* __restrict__ mu0,   const float* __restrict__ Sig0,
             const float* __restrict__ alpha0,const float* __restrict__ h0,
             const float* __restrict__ u_f,   const float* __restrict__ eps_g,
             const float* __restrict__ Abase, const float* __restrict__ Bbase,
             const float* __restrict__ Cbase, const float* __restrict__ Qm,
             const float* __restrict__ Wx,    const float* __restrict__ Wh,
             const float* __restrict__ bx,    const float* __restrict__ bh,
             const float* __restrict__ Wo,    const float* __restrict__ bo,
             float* __restrict__ out)
{
    __shared__ Smem sm;
    const int b    = blockIdx.x;
    const int tid  = threadIdx.x;
    const int lane = tid & 31;
    const int wid  = tid >> 5;
    const int i_row = tid >> 3;        // 0..31
    const int j0    = (tid & 7) * 4;   // 0,4,...,28

    // ---- init: persistent state + Q + Sigma0
    if (tid < DZ)   sm.mu[tid]    = mu0[b * DZ + tid];
    if (tid < KMIX) sm.alpha[tid] = alpha0[b * KMIX + tid];
    if (tid >= 32 && tid < 96) sm.h[tid - 32] = h0[b * HID + (tid - 32)];
    {
        float4 q4 = *(const float4*)(Qm + i_row * DZ + j0);
        *(float4*)&sm.Q[i_row][j0] = q4;
        float4 s4 = *(const float4*)(Sig0 + (unsigned)b * 1024u + i_row * DZ + j0);
        *(float4*)&sm.S[i_row][j0] = s4;
    }
    __syncthreads();
    if (wid == 0) chol32_warp(sm, lane);   // L0 = chol(Sigma0); z garbage (unused)
    __syncthreads();

    const unsigned bt0 = (unsigned)b * TLEN;

    for (int t = 0; t < TLEN; ++t) {
        const unsigned bt = bt0 + (unsigned)t;

        // ===== stage A: mixtures A_t/B_t/C_t, load u/eps ======================
        {
            float al0 = sm.alpha[0], al1 = sm.alpha[1], al2 = sm.alpha[2], al3 = sm.alpha[3];
            const float4* A4 = (const float4*)Abase;
            float4 x  = A4[tid];
            float4 at = make_float4(al0*x.x, al0*x.y, al0*x.z, al0*x.w);
            x = A4[256 + tid];
            at.x = fmaf(al1, x.x, at.x); at.y = fmaf(al1, x.y, at.y);
            at.z = fmaf(al1, x.z, at.z); at.w = fmaf(al1, x.w, at.w);
            x = A4[512 + tid];
            at.x = fmaf(al2, x.x, at.x); at.y = fmaf(al2, x.y, at.y);
            at.z = fmaf(al2, x.z, at.z); at.w = fmaf(al2, x.w, at.w);
            x = A4[768 + tid];
            at.x = fmaf(al3, x.x, at.x); at.y = fmaf(al3, x.y, at.y);
            at.z = fmaf(al3, x.z, at.z); at.w = fmaf(al3, x.w, at.w);
            *(float4*)&sm.A[i_row][j0] = at;
            *(float4*)(out + OFF_AT + bt * 1024u + (unsigned)tid * 4u) = at;

            float bv = al0 * Bbase[tid];
            bv = fmaf(al1, Bbase[256 + tid], bv);
            bv = fmaf(al2, Bbase[512 + tid], bv);
            bv = fmaf(al3, Bbase[768 + tid], bv);
            ((float*)sm.Bt)[tid] = bv;
            out[OFF_BT + bt * 256u + (unsigned)tid] = bv;

            const float2* C2 = (const float2*)Cbase;
            float2 c  = C2[tid];
            float2 ct = make_float2(al0*c.x, al0*c.y);
            c = C2[256 + tid]; ct.x = fmaf(al1, c.x, ct.x); ct.y = fmaf(al1, c.y, ct.y);
            c = C2[512 + tid]; ct.x = fmaf(al2, c.x, ct.x); ct.y = fmaf(al2, c.y, ct.y);
            c = C2[768 + tid]; ct.x = fmaf(al3, c.x, ct.x); ct.y = fmaf(al3, c.y, ct.y);
            int crow = (2 * tid) >> 5, ccol = (2 * tid) & 31;
            *(float2*)&sm.Ct[crow][ccol] = ct;
            *(float2*)(out + OFF_CT + bt * 512u + (unsigned)tid * 2u) = ct;

            if (tid < DZ)            sm.eps[tid]    = eps_g[bt * 32u + (unsigned)tid];
            else if (tid < DZ + DU)  sm.u[tid - DZ] = u_f[bt * 8u + (unsigned)(tid - DZ)];
        }
        __syncthreads();

        // ===== stage B: G = A_t @ L ; mu_next = A_t mu + B_t u ================
        {
            float g0 = 0.f, g1 = 0.f, g2 = 0.f, g3 = 0.f;
#pragma unroll
            for (int k0 = 0; k0 < DZ; k0 += 4) {
                float4 ar = *(const float4*)&sm.A[i_row][k0];
                float4 l0 = *(const float4*)&sm.L[k0 + 0][j0];
                float4 l1 = *(const float4*)&sm.L[k0 + 1][j0];
                float4 l2 = *(const float4*)&sm.L[k0 + 2][j0];
                float4 l3 = *(const float4*)&sm.L[k0 + 3][j0];
                g0 = fmaf(ar.x, l0.x, fmaf(ar.y, l1.x, fmaf(ar.z, l2.x, fmaf(ar.w, l3.x, g0))));
                g1 = fmaf(ar.x, l0.y, fmaf(ar.y, l1.y, fmaf(ar.z, l2.y, fmaf(ar.w, l3.y, g1))));
                g2 = fmaf(ar.x, l0.z, fmaf(ar.y, l1.z, fmaf(ar.z, l2.z, fmaf(ar.w, l3.z, g2))));
                g3 = fmaf(ar.x, l0.w, fmaf(ar.y, l1.w, fmaf(ar.z, l2.w, fmaf(ar.w, l3.w, g3))));
            }
            *(float4*)&sm.G[i_row][j0] = make_float4(g0, g1, g2, g3);
            if (tid < DZ) {
                float acc = 0.f;
#pragma unroll 8
                for (int k = 0; k < DZ; ++k) acc = fmaf(sm.A[tid][k], sm.mu[k], acc);
#pragma unroll
                for (int k = 0; k < DU; ++k) acc = fmaf(sm.Bt[tid][k], sm.u[k], acc);
                sm.mun[tid] = acc;
                out[OFF_MU + bt * 32u + (unsigned)tid] = acc;
            }
        }
        __syncthreads();

        // ===== stage C: S = G G^T + Q =========================================
        {
            float s0 = 0.f, s1 = 0.f, s2 = 0.f, s3 = 0.f;
#pragma unroll
            for (int k0 = 0; k0 < DZ; k0 += 4) {
                float4 gi = *(const float4*)&sm.G[i_row][k0];
                float4 q0 = *(const float4*)&sm.G[j0 + 0][k0];
                float4 q1 = *(const float4*)&sm.G[j0 + 1][k0];
                float4 q2 = *(const float4*)&sm.G[j0 + 2][k0];
                float4 q3 = *(const float4*)&sm.G[j0 + 3][k0];
                s0 = fmaf(gi.x, q0.x, fmaf(gi.y, q0.y, fmaf(gi.z, q0.z, fmaf(gi.w, q0.w, s0))));
                s1 = fmaf(gi.x, q1.x, fmaf(gi.y, q1.y, fmaf(gi.z, q1.z, fmaf(gi.w, q1.w, s1))));
                s2 = fmaf(gi.x, q2.x, fmaf(gi.y, q2.y, fmaf(gi.z, q2.z, fmaf(gi.w, q2.w, s2))));
                s3 = fmaf(gi.x, q3.x, fmaf(gi.y, q3.y, fmaf(gi.z, q3.z, fmaf(gi.w, q3.w, s3))));
            }
            float4 qq = *(const float4*)&sm.Q[i_row][j0];
            *(float4*)&sm.S[i_row][j0] = make_float4(s0 + qq.x, s1 + qq.y, s2 + qq.z, s3 + qq.w);
        }
        __syncthreads();

        // ===== stage D: warp0 chol (+fused z); warps1-7 store Sig + gh ========
        if (wid == 0) {
            chol32_warp(sm, lane);
        } else {
            int c = tid - 32;                       // 0..223 of 256 float4 chunks
            {
                int ci = c >> 3, cj = (c & 7) * 4;
                float4 v = *(const float4*)&sm.S[ci][cj];
                *(float4*)(out + OFF_SIG + bt * 1024u + (unsigned)c * 4u) = v;
            }
            if (c < 32) {
                int c2 = c + 224;
                int ci = c2 >> 3, cj = (c2 & 7) * 4;
                float4 v = *(const float4*)&sm.S[ci][cj];
                *(float4*)(out + OFF_SIG + bt * 1024u + (unsigned)c2 * 4u) = v;
            }
            if (tid < 32 + G3) {                    // gh = h @ Wh + bh (indep of z)
                int g = tid - 32;
                float acc = bh[g];
#pragma unroll 4
                for (int hh = 0; hh < HID; ++hh)
                    acc = fmaf(sm.h[hh], Wh[hh * G3 + g], acc);
                sm.gh[g] = acc;
            }
        }
        __syncthreads();

        // ===== stage E: z store + mu roll; gx = z@Wx + bx; a_t = C_t z ========
        if (tid < 32) {
            out[OFF_Z + bt * 32u + (unsigned)tid] = sm.z[tid];
            sm.mu[tid] = sm.mun[tid];
        } else if (tid < 224) {
            int g = tid - 32;
            float acc = bx[g];
#pragma unroll 4
            for (int k = 0; k < DZ; ++k)
                acc = fmaf(sm.z[k], Wx[k * G3 + g], acc);
            sm.gx[g] = acc;
        } else if (tid < 224 + DA) {
            int r = tid - 224;
            float acc = 0.f;
#pragma unroll 8
            for (int k = 0; k < DZ; ++k) acc = fmaf(sm.Ct[r][k], sm.z[k], acc);
            out[OFF_A + bt * 16u + (unsigned)r] = acc;
        }
        __syncthreads();

        // ===== stage F (warp0): GRU nonlinearity + softmax -> alpha ===========
        if (wid == 0) {
            float p0 = 0.f, p1 = 0.f, p2 = 0.f, p3 = 0.f;
#pragma unroll
            for (int s = 0; s < 2; ++s) {
                int hh = lane + s * 32;
                float xr = sm.gx[hh], xz = sm.gx[64 + hh], xn = sm.gx[128 + hh];
                float hr = sm.gh[hh], hz = sm.gh[64 + hh], hn = sm.gh[128 + hh];
                float r  = 1.f / (1.f + __expf(-(xr + hr)));
                float zg = 1.f / (1.f + __expf(-(xz + hz)));
                float n  = tanhf(xn + r * hn);
                float hv = (1.f - zg) * n + zg * sm.h[hh];
                sm.h[hh] = hv;
                p0 = fmaf(hv, Wo[hh * 4 + 0], p0);
                p1 = fmaf(hv, Wo[hh * 4 + 1], p1);
                p2 = fmaf(hv, Wo[hh * 4 + 2], p2);
                p3 = fmaf(hv, Wo[hh * 4 + 3], p3);
            }
#pragma unroll
            for (int off = 16; off; off >>= 1) {
                p0 += __shfl_xor_sync(0xffffffffu, p0, off);
                p1 += __shfl_xor_sync(0xffffffffu, p1, off);
                p2 += __shfl_xor_sync(0xffffffffu, p2, off);
                p3 += __shfl_xor_sync(0xffffffffu, p3, off);
            }
            float o0 = p0 + bo[0], o1 = p1 + bo[1], o2 = p2 + bo[2], o3 = p3 + bo[3];
            float m  = fmaxf(fmaxf(o0, o1), fmaxf(o2, o3));
            float e0 = __expf(o0 - m), e1 = __expf(o1 - m);
            float e2 = __expf(o2 - m), e3 = __expf(o3 - m);
            float s  = e0 + e1 + e2 + e3;
            if (lane == 0) {
                sm.alpha[0] = e0 / s; sm.alpha[1] = e1 / s;
                sm.alpha[2] = e2 / s; sm.alpha[3] = e3 / s;
            }
        }
        __syncthreads();
    }
}

extern "C" void kernel_launch(void* const* d_in, const int* in_sizes, int n_in,
                              void* d_out, int out_size)
{
    lgssm_kernel<<<NBATCH, 256>>>(
        (const float*)d_in[0],  (const float*)d_in[1],  (const float*)d_in[2],
        (const float*)d_in[3],  (const float*)d_in[4],  (const float*)d_in[5],
        (const float*)d_in[6],  (const float*)d_in[7],  (const float*)d_in[8],
        (const float*)d_in[9],  (const float*)d_in[10], (const float*)d_in[11],
        (const float*)d_in[12], (const float*)d_in[13], (const float*)d_in[14],
        (const float*)d_in[15], (float*)d_out);
}

// round 4
// speedup vs baseline: 1.6548x; 1.6548x over previous
#include <cuda_runtime.h>

#define NBATCH 256
#define TLEN   256
#define DZ     32
#define DA     16
#define DU     8
#define KMIX   4
#define HID    64
#define G3     192   // 3*HID
#define SPAD   36
#define NTHR   128

// output segment offsets (floats); order: z, mu, Sig, a, A_t, B_t, C_t
#define OFF_Z   0u
#define OFF_MU  2097152u
#define OFF_SIG 4194304u
#define OFF_A   71303168u
#define OFF_AT  72351744u
#define OFF_BT  139460608u
#define OFF_CT  156237824u

struct Smem {
    float A[DZ][SPAD];
    float L[DZ][SPAD];
    float G[DZ][SPAD];
    float S[DZ][SPAD];
    float Q[DZ][SPAD];
    float Ct[DA][SPAD];
    float Bt[DZ][DU];
    float mu[DZ];
    float mun[DZ];
    float h[HID];
    float z[DZ];
    float eps[DZ];
    float u[DU];
    float gh[G3];
    float gx[G3];
    float alpha[KMIX];
};

__device__ __forceinline__ float fast_tanh(float x) {
    float y;
    asm("tanh.approx.f32 %0, %1;" : "=f"(y) : "f"(x));
    return y;
}
__device__ __forceinline__ float fast_sigmoid(float x) {
    return 0.5f + 0.5f * fast_tanh(0.5f * x);
}

// Warp 0 (lane = row): in-register Cholesky of sm.S -> sm.L,
// fused z = mu_next + L @ eps.
__device__ __forceinline__ void chol32_warp(Smem& sm, int lane)
{
    float a[DZ];
#pragma unroll
    for (int k = 0; k < DZ; ++k) a[k] = sm.S[lane][k];
    float eps_own = sm.eps[lane];
    float zacc    = sm.mun[lane];
#pragma unroll
    for (int j = 0; j < DZ; ++j) {
        float d   = __shfl_sync(0xffffffffu, a[j], j);
        float rs  = rsqrtf(d);
        float lij = a[j] * rs;
        a[j] = lij;
        float ej = __shfl_sync(0xffffffffu, eps_own, j);
        if (lane >= j) zacc = fmaf(lij, ej, zacc);
        float lsq = lij * lij;
#pragma unroll
        for (int k = j + 1; k < DZ; ++k) {
            float lkj = __shfl_sync(0xffffffffu, lij, k);
            if (k == lane) a[k] -= lsq;          // own diag: no shfl dependency
            else           a[k] = fmaf(-lij, lkj, a[k]);
        }
    }
#pragma unroll
    for (int k = 0; k < DZ; ++k) sm.L[lane][k] = (k <= lane) ? a[k] : 0.f;
    sm.z[lane] = zacc;
}

__global__ void __launch_bounds__(NTHR, 2)
lgssm_kernel(const float* __restrict__ mu0,   const float* __restrict__ Sig0,
             const float* __restrict__ alpha0,const float* __restrict__ h0,
             const float* __restrict__ u_f,   const float* __restrict__ eps_g,
             const float* __restrict__ Abase, const float* __restrict__ Bbase,
             const float* __restrict__ Cbase, const float* __restrict__ Qm,
             const float* __restrict__ Wx,    const float* __restrict__ Wh,
             const float* __restrict__ bx,    const float* __restrict__ bh,
             const float* __restrict__ Wo,    const float* __restrict__ bo,
             float* __restrict__ out)
{
    __shared__ Smem sm;
    const int b    = blockIdx.x;
    const int tid  = threadIdx.x;
    const int lane = tid & 31;
    const int wid  = tid >> 5;
    const int i_row = tid >> 2;        // 0..31 (stage B/C: 8 outputs/thread)
    const int j0    = (tid & 3) * 8;   // 0,8,16,24

    // ---- init
    if (tid < DZ)   sm.mu[tid]    = mu0[b * DZ + tid];
    if (tid < KMIX) sm.alpha[tid] = alpha0[b * KMIX + tid];
    if (tid >= 32 && tid < 96) sm.h[tid - 32] = h0[b * HID + (tid - 32)];
#pragma unroll
    for (int s = 0; s < 2; ++s) {
        int c = tid + s * NTHR;                 // 0..255 float4 chunks
        int ci = c >> 3, cj = (c & 7) * 4;
        *(float4*)&sm.Q[ci][cj] = *(const float4*)(Qm + c * 4);
        *(float4*)&sm.S[ci][cj] = *(const float4*)(Sig0 + (unsigned)b * 1024u + c * 4);
    }
    __syncthreads();
    if (wid == 0) chol32_warp(sm, lane);        // L0 = chol(Sigma0)
    __syncthreads();

    const unsigned bt0 = (unsigned)b * TLEN;

    for (int t = 0; t < TLEN; ++t) {
        const unsigned bt = bt0 + (unsigned)t;

        // ===== stage A: mixtures A_t/B_t/C_t, load u/eps ======================
        {
            float al0 = sm.alpha[0], al1 = sm.alpha[1], al2 = sm.alpha[2], al3 = sm.alpha[3];
            const float4* A4 = (const float4*)Abase;
#pragma unroll
            for (int s = 0; s < 2; ++s) {
                int idx = tid + s * NTHR;       // 0..255
                float4 x0 = A4[idx],       x1 = A4[256 + idx];
                float4 x2 = A4[512 + idx], x3 = A4[768 + idx];
                float4 at;
                at.x = al0*x0.x + al1*x1.x + al2*x2.x + al3*x3.x;
                at.y = al0*x0.y + al1*x1.y + al2*x2.y + al3*x3.y;
                at.z = al0*x0.z + al1*x1.z + al2*x2.z + al3*x3.z;
                at.w = al0*x0.w + al1*x1.w + al2*x2.w + al3*x3.w;
                *(float4*)&sm.A[idx >> 3][(idx & 7) * 4] = at;
                *(float4*)(out + OFF_AT + bt * 1024u + (unsigned)idx * 4u) = at;
            }
#pragma unroll
            for (int s = 0; s < 2; ++s) {
                int idx = tid + s * NTHR;       // 0..255
                float bv = al0 * Bbase[idx]       + al1 * Bbase[256 + idx]
                         + al2 * Bbase[512 + idx] + al3 * Bbase[768 + idx];
                ((float*)sm.Bt)[idx] = bv;
                out[OFF_BT + bt * 256u + (unsigned)idx] = bv;
            }
            {
                const float4* C4 = (const float4*)Cbase;
                float4 c0 = C4[tid],       c1 = C4[128 + tid];
                float4 c2 = C4[256 + tid], c3 = C4[384 + tid];
                float4 ct;
                ct.x = al0*c0.x + al1*c1.x + al2*c2.x + al3*c3.x;
                ct.y = al0*c0.y + al1*c1.y + al2*c2.y + al3*c3.y;
                ct.z = al0*c0.z + al1*c1.z + al2*c2.z + al3*c3.z;
                ct.w = al0*c0.w + al1*c1.w + al2*c2.w + al3*c3.w;
                *(float4*)&sm.Ct[tid >> 3][(tid & 7) * 4] = ct;
                *(float4*)(out + OFF_CT + bt * 512u + (unsigned)tid * 4u) = ct;
            }
            if (tid < DZ)            sm.eps[tid]    = eps_g[bt * 32u + (unsigned)tid];
            else if (tid < DZ + DU)  sm.u[tid - DZ] = u_f[bt * 8u + (unsigned)(tid - DZ)];
        }
        __syncthreads();

        // ===== stage B: G = A_t @ L (8 outputs/thread); mu_next ===============
        {
            float g0=0.f,g1=0.f,g2=0.f,g3=0.f,g4=0.f,g5=0.f,g6=0.f,g7=0.f;
#pragma unroll
            for (int k0 = 0; k0 < DZ; k0 += 4) {
                float4 ar = *(const float4*)&sm.A[i_row][k0];
#pragma unroll
                for (int r = 0; r < 4; ++r) {
                    float av = (r == 0) ? ar.x : (r == 1) ? ar.y : (r == 2) ? ar.z : ar.w;
                    float4 lo = *(const float4*)&sm.L[k0 + r][j0];
                    float4 hi = *(const float4*)&sm.L[k0 + r][j0 + 4];
                    g0 = fmaf(av, lo.x, g0); g1 = fmaf(av, lo.y, g1);
                    g2 = fmaf(av, lo.z, g2); g3 = fmaf(av, lo.w, g3);
                    g4 = fmaf(av, hi.x, g4); g5 = fmaf(av, hi.y, g5);
                    g6 = fmaf(av, hi.z, g6); g7 = fmaf(av, hi.w, g7);
                }
            }
            *(float4*)&sm.G[i_row][j0]     = make_float4(g0, g1, g2, g3);
            *(float4*)&sm.G[i_row][j0 + 4] = make_float4(g4, g5, g6, g7);
            if (tid < DZ) {                       // mu_next = A_t mu + B_t u
                float acc = 0.f;
#pragma unroll
                for (int k0 = 0; k0 < DZ; k0 += 4) {
                    float4 a4 = *(const float4*)&sm.A[tid][k0];
                    float4 m4 = *(const float4*)&sm.mu[k0];
                    acc = fmaf(a4.x, m4.x, fmaf(a4.y, m4.y, fmaf(a4.z, m4.z, fmaf(a4.w, m4.w, acc))));
                }
#pragma unroll
                for (int k0 = 0; k0 < DU; k0 += 4) {
                    float4 b4 = *(const float4*)&sm.Bt[tid][k0];
                    float4 u4 = *(const float4*)&sm.u[k0];
                    acc = fmaf(b4.x, u4.x, fmaf(b4.y, u4.y, fmaf(b4.z, u4.z, fmaf(b4.w, u4.w, acc))));
                }
                sm.mun[tid] = acc;
                out[OFF_MU + bt * 32u + (unsigned)tid] = acc;
            }
        }
        __syncthreads();

        // ===== stage C: S = G G^T + Q (8 outputs/thread) ======================
        {
            float s0=0.f,s1=0.f,s2=0.f,s3=0.f,s4=0.f,s5=0.f,s6=0.f,s7=0.f;
#pragma unroll
            for (int k0 = 0; k0 < DZ; k0 += 4) {
                float4 gi = *(const float4*)&sm.G[i_row][k0];
#pragma unroll
                for (int r = 0; r < 8; ++r) {
                    float4 gr = *(const float4*)&sm.G[j0 + r][k0];
                    float pv = fmaf(gi.x, gr.x, fmaf(gi.y, gr.y, fmaf(gi.z, gr.z, gi.w * gr.w)));
                    if      (r == 0) s0 += pv; else if (r == 1) s1 += pv;
                    else if (r == 2) s2 += pv; else if (r == 3) s3 += pv;
                    else if (r == 4) s4 += pv; else if (r == 5) s5 += pv;
                    else if (r == 6) s6 += pv; else               s7 += pv;
                }
            }
            float4 qlo = *(const float4*)&sm.Q[i_row][j0];
            float4 qhi = *(const float4*)&sm.Q[i_row][j0 + 4];
            *(float4*)&sm.S[i_row][j0]     = make_float4(s0+qlo.x, s1+qlo.y, s2+qlo.z, s3+qlo.w);
            *(float4*)&sm.S[i_row][j0 + 4] = make_float4(s4+qhi.x, s5+qhi.y, s6+qhi.z, s7+qhi.w);
        }
        __syncthreads();

        // ===== stage D: warp0 chol(+z); warps1-3 store Sig + compute gh =======
        if (wid == 0) {
            chol32_warp(sm, lane);
        } else {
            int c = tid - 32;                      // 0..95
#pragma unroll
            for (int s = 0; s < 3; ++s) {
                int cc = c + s * 96;
                if (cc < 256) {
                    int ci = cc >> 3, cj = (cc & 7) * 4;
                    float4 v = *(const float4*)&sm.S[ci][cj];
                    *(float4*)(out + OFF_SIG + bt * 1024u + (unsigned)cc * 4u) = v;
                }
            }
#pragma unroll
            for (int s = 0; s < 2; ++s) {          // gh = h @ Wh + bh
                int g = (tid - 32) + s * 96;       // 0..191
                float acc = bh[g];
#pragma unroll 4
                for (int hh = 0; hh < HID; ++hh)
                    acc = fmaf(sm.h[hh], Wh[hh * G3 + g], acc);
                sm.gh[g] = acc;
            }
        }
        __syncthreads();

        // ===== stage E: z/a_t out, mu roll, gx = z@Wx + bx ====================
        if (tid < 32) {
            out[OFF_Z + bt * 32u + (unsigned)tid] = sm.z[tid];
            sm.mu[tid] = sm.mun[tid];
            if (tid < DA) {                        // a_t = C_t z
                float acc = 0.f;
#pragma unroll
                for (int k0 = 0; k0 < DZ; k0 += 4) {
                    float4 c4 = *(const float4*)&sm.Ct[tid][k0];
                    float4 z4 = *(const float4*)&sm.z[k0];
                    acc = fmaf(c4.x, z4.x, fmaf(c4.y, z4.y, fmaf(c4.z, z4.z, fmaf(c4.w, z4.w, acc))));
                }
                out[OFF_A + bt * 16u + (unsigned)tid] = acc;
            }
        } else {
#pragma unroll
            for (int s = 0; s < 2; ++s) {
                int g = (tid - 32) + s * 96;       // 0..191
                float acc = bx[g];
#pragma unroll 4
                for (int k = 0; k < DZ; ++k)
                    acc = fmaf(sm.z[k], Wx[k * G3 + g], acc);
                sm.gx[g] = acc;
            }
        }
        __syncthreads();

        // ===== stage F (warp0): GRU nonlinearity + softmax -> alpha ===========
        if (wid == 0) {
            float p0 = 0.f, p1 = 0.f, p2 = 0.f, p3 = 0.f;
#pragma unroll
            for (int s = 0; s < 2; ++s) {
                int hh = lane + s * 32;
                float xr = sm.gx[hh], xz = sm.gx[64 + hh], xn = sm.gx[128 + hh];
                float hr = sm.gh[hh], hz = sm.gh[64 + hh], hn = sm.gh[128 + hh];
                float r  = fast_sigmoid(xr + hr);
                float zg = fast_sigmoid(xz + hz);
                float n  = fast_tanh(xn + r * hn);
                float hv = (1.f - zg) * n + zg * sm.h[hh];
                sm.h[hh] = hv;
                p0 = fmaf(hv, Wo[hh * 4 + 0], p0);
                p1 = fmaf(hv, Wo[hh * 4 + 1], p1);
                p2 = fmaf(hv, Wo[hh * 4 + 2], p2);
                p3 = fmaf(hv, Wo[hh * 4 + 3], p3);
            }
#pragma unroll
            for (int off = 16; off; off >>= 1) {
                p0 += __shfl_xor_sync(0xffffffffu, p0, off);
                p1 += __shfl_xor_sync(0xffffffffu, p1, off);
                p2 += __shfl_xor_sync(0xffffffffu, p2, off);
                p3 += __shfl_xor_sync(0xffffffffu, p3, off);
            }
            float o0 = p0 + bo[0], o1 = p1 + bo[1], o2 = p2 + bo[2], o3 = p3 + bo[3];
            float m  = fmaxf(fmaxf(o0, o1), fmaxf(o2, o3));
            float e0 = __expf(o0 - m), e1 = __expf(o1 - m);
            float e2 = __expf(o2 - m), e3 = __expf(o3 - m);
            float s  = e0 + e1 + e2 + e3;
            if (lane == 0) {
                float inv = 1.f / s;
                sm.alpha[0] = e0 * inv; sm.alpha[1] = e1 * inv;
                sm.alpha[2] = e2 * inv; sm.alpha[3] = e3 * inv;
            }
        }
        __syncthreads();
    }
}

extern "C" void kernel_launch(void* const* d_in, const int* in_sizes, int n_in,
                              void* d_out, int out_size)
{
    lgssm_kernel<<<NBATCH, NTHR>>>(
        (const float*)d_in[0],  (const float*)d_in[1],  (const float*)d_in[2],
        (const float*)d_in[3],  (const float*)d_in[4],  (const float*)d_in[5],
        (const float*)d_in[6],  (const float*)d_in[7],  (const float*)d_in[8],
        (const float*)d_in[9],  (const float*)d_in[10], (const float*)d_in[11],
        (const float*)d_in[12], (const float*)d_in[13], (const float*)d_in[14],
        (const float*)d_in[15], (float*)d_out);
}

// round 5
// speedup vs baseline: 1.7164x; 1.0372x over previous
#include <cuda_runtime.h>

#define NBATCH 256
#define TLEN   256
#define DZ     32
#define DA     16
#define DU     8
#define KMIX   4
#define HID    64
#define G3     192
#define SPAD   36
#define NTHR   256   // 2 chains x 128 threads

// output segment offsets (floats); order: z, mu, Sig, a, A_t, B_t, C_t
#define OFF_Z   0u
#define OFF_MU  2097152u
#define OFF_SIG 4194304u
#define OFF_A   71303168u
#define OFF_AT  72351744u
#define OFF_BT  139460608u
#define OFF_CT  156237824u

struct Chain {
    float A[DZ][SPAD];
    float L[DZ][SPAD];
    float G[DZ][SPAD];
    float S[DZ][SPAD];
    float Ct[DA][SPAD];
    float Bt[DZ][DU];
    float mu[DZ], mun[DZ], z[DZ], eps[DZ];
    float u[DU];
    float h[HID];
    float gh[G3], gx[G3];
    float alpha[KMIX];
};

struct Shared {
    float Wh[HID * G3];   // 48 KB
    float Wx[DZ * G3];    // 24 KB
    float Am[KMIX * 1024];// 16 KB
    float Cm[KMIX * 512]; //  8 KB
    float Bm[KMIX * 256]; //  4 KB
    float Qm[1024];       //  4 KB
    float Wo[HID * KMIX]; //  1 KB
    float bx[G3], bh[G3];
    float bo[KMIX];
    Chain cs[2];
};

__device__ __forceinline__ float fast_tanh(float x) {
    float y;
    asm("tanh.approx.f32 %0, %1;" : "=f"(y) : "f"(x));
    return y;
}
__device__ __forceinline__ float fast_sigmoid(float x) {
    return 0.5f + 0.5f * fast_tanh(0.5f * x);
}

// One warp (lane = row): in-register Cholesky of C.S -> C.L,
// fused z = mu_next + L @ eps.
__device__ __forceinline__ void chol32_warp(Chain& C, int lane)
{
    float a[DZ];
#pragma unroll
    for (int k = 0; k < DZ; ++k) a[k] = C.S[lane][k];
    float eps_own = C.eps[lane];
    float zacc    = C.mun[lane];
#pragma unroll
    for (int j = 0; j < DZ; ++j) {
        float d   = __shfl_sync(0xffffffffu, a[j], j);
        float rs  = rsqrtf(d);
        float lij = a[j] * rs;
        a[j] = lij;
        float ej = __shfl_sync(0xffffffffu, eps_own, j);
        if (lane >= j) zacc = fmaf(lij, ej, zacc);
        float lsq = lij * lij;
#pragma unroll
        for (int k = j + 1; k < DZ; ++k) {
            float lkj = __shfl_sync(0xffffffffu, lij, k);
            if (k == lane) a[k] -= lsq;          // own diag: off the shfl chain
            else           a[k] = fmaf(-lij, lkj, a[k]);
        }
    }
#pragma unroll
    for (int k = 0; k < DZ; ++k) C.L[lane][k] = (k <= lane) ? a[k] : 0.f;
    C.z[lane] = zacc;
}

__global__ void __launch_bounds__(NTHR, 1)
lgssm_kernel(const float* __restrict__ mu0,   const float* __restrict__ Sig0,
             const float* __restrict__ alpha0,const float* __restrict__ h0,
             const float* __restrict__ u_f,   const float* __restrict__ eps_g,
             const float* __restrict__ Abase, const float* __restrict__ Bbase,
             const float* __restrict__ Cbase, const float* __restrict__ Qm,
             const float* __restrict__ Wx,    const float* __restrict__ Wh,
             const float* __restrict__ bx,    const float* __restrict__ bh,
             const float* __restrict__ Wo,    const float* __restrict__ bo,
             float* __restrict__ out)
{
    extern __shared__ float smem_f[];
    Shared& sh = *reinterpret_cast<Shared*>(smem_f);

    const int tid   = threadIdx.x;
    const int lane  = tid & 31;
    const int chain = tid >> 7;         // 0/1
    const int ct    = tid & 127;        // thread within chain
    const int lw    = (tid >> 5) & 3;   // warp within chain
    Chain& C = sh.cs[chain];

    const unsigned b   = (unsigned)blockIdx.x * 2u + (unsigned)chain;
    const int i_row = ct >> 2;          // 0..31
    const int j0    = (ct & 3) * 8;     // 0,8,16,24

    // ---- one-time: weights -> smem (whole CTA cooperates)
    for (int i = tid; i < HID * G3;   i += NTHR) sh.Wh[i] = Wh[i];
    for (int i = tid; i < DZ * G3;    i += NTHR) sh.Wx[i] = Wx[i];
    for (int i = tid; i < KMIX * 1024;i += NTHR) sh.Am[i] = Abase[i];
    for (int i = tid; i < KMIX * 512; i += NTHR) sh.Cm[i] = Cbase[i];
    for (int i = tid; i < KMIX * 256; i += NTHR) sh.Bm[i] = Bbase[i];
    for (int i = tid; i < 1024;       i += NTHR) sh.Qm[i] = Qm[i];
    if (tid < HID * KMIX) sh.Wo[tid] = Wo[tid];
    if (tid < G3) { sh.bx[tid] = bx[tid]; sh.bh[tid] = bh[tid]; }
    if (tid < KMIX) sh.bo[tid] = bo[tid];

    // ---- per-chain init
    if (ct < DZ)   C.mu[ct]    = mu0[b * DZ + ct];
    if (ct < KMIX) C.alpha[ct] = alpha0[b * KMIX + ct];
    if (ct >= 32 && ct < 96) C.h[ct - 32] = h0[b * HID + (ct - 32)];
#pragma unroll
    for (int s = 0; s < 2; ++s) {
        int c = ct + s * 128;           // 0..255 float4 chunks
        *(float4*)&C.S[c >> 3][(c & 7) * 4] =
            *(const float4*)(Sig0 + b * 1024u + (unsigned)c * 4u);
    }

    // prefetch eps/u for t=0
    float pf_eps = 0.f, pf_u = 0.f;
    if (ct < DZ)                pf_eps = eps_g[(b * TLEN) * 32u + (unsigned)ct];
    else if (ct < DZ + DU)      pf_u   = u_f[(b * TLEN) * 8u + (unsigned)(ct - DZ)];

    __syncthreads();
    if (lw == 0) chol32_warp(C, lane);   // L0 = chol(Sigma0); z unused
    __syncthreads();

#pragma unroll 1
    for (int t = 0; t < TLEN; ++t) {
        const unsigned bt = b * TLEN + (unsigned)t;
        const unsigned tn = (t < TLEN - 1) ? bt + 1u : bt;

        // ===== stage A: mixtures from smem; eps/u from prefetch ===============
        {
            float al0 = C.alpha[0], al1 = C.alpha[1], al2 = C.alpha[2], al3 = C.alpha[3];
            const float4* A4 = (const float4*)sh.Am;
#pragma unroll
            for (int s = 0; s < 2; ++s) {
                int idx = ct + s * 128;
                float4 x0 = A4[idx],       x1 = A4[256 + idx];
                float4 x2 = A4[512 + idx], x3 = A4[768 + idx];
                float4 at;
                at.x = al0*x0.x + al1*x1.x + al2*x2.x + al3*x3.x;
                at.y = al0*x0.y + al1*x1.y + al2*x2.y + al3*x3.y;
                at.z = al0*x0.z + al1*x1.z + al2*x2.z + al3*x3.z;
                at.w = al0*x0.w + al1*x1.w + al2*x2.w + al3*x3.w;
                *(float4*)&C.A[idx >> 3][(idx & 7) * 4] = at;
                *(float4*)(out + OFF_AT + bt * 1024u + (unsigned)idx * 4u) = at;
            }
            {
                const float4* C4 = (const float4*)sh.Cm;
                float4 c0 = C4[ct],       c1 = C4[128 + ct];
                float4 c2 = C4[256 + ct], c3 = C4[384 + ct];
                float4 cc;
                cc.x = al0*c0.x + al1*c1.x + al2*c2.x + al3*c3.x;
                cc.y = al0*c0.y + al1*c1.y + al2*c2.y + al3*c3.y;
                cc.z = al0*c0.z + al1*c1.z + al2*c2.z + al3*c3.z;
                cc.w = al0*c0.w + al1*c1.w + al2*c2.w + al3*c3.w;
                *(float4*)&C.Ct[ct >> 3][(ct & 7) * 4] = cc;
                *(float4*)(out + OFF_CT + bt * 512u + (unsigned)ct * 4u) = cc;
            }
#pragma unroll
            for (int s = 0; s < 2; ++s) {
                int idx = ct + s * 128;
                float bv = al0 * sh.Bm[idx]       + al1 * sh.Bm[256 + idx]
                         + al2 * sh.Bm[512 + idx] + al3 * sh.Bm[768 + idx];
                ((float*)C.Bt)[idx] = bv;
                out[OFF_BT + bt * 256u + (unsigned)idx] = bv;
            }
            if (ct < DZ) {
                C.eps[ct] = pf_eps;
                pf_eps = eps_g[tn * 32u + (unsigned)ct];
            } else if (ct < DZ + DU) {
                C.u[ct - DZ] = pf_u;
                pf_u = u_f[tn * 8u + (unsigned)(ct - DZ)];
            }
        }
        __syncthreads();

        // ===== stage B: G = A_t @ L (8 out/thread); mu_next ===================
        {
            float g0=0.f,g1=0.f,g2=0.f,g3=0.f,g4=0.f,g5=0.f,g6=0.f,g7=0.f;
#pragma unroll
            for (int k0 = 0; k0 < DZ; k0 += 4) {
                float4 ar = *(const float4*)&C.A[i_row][k0];
#pragma unroll
                for (int r = 0; r < 4; ++r) {
                    float av = (r == 0) ? ar.x : (r == 1) ? ar.y : (r == 2) ? ar.z : ar.w;
                    float4 lo = *(const float4*)&C.L[k0 + r][j0];
                    float4 hi = *(const float4*)&C.L[k0 + r][j0 + 4];
                    g0 = fmaf(av, lo.x, g0); g1 = fmaf(av, lo.y, g1);
                    g2 = fmaf(av, lo.z, g2); g3 = fmaf(av, lo.w, g3);
                    g4 = fmaf(av, hi.x, g4); g5 = fmaf(av, hi.y, g5);
                    g6 = fmaf(av, hi.z, g6); g7 = fmaf(av, hi.w, g7);
                }
            }
            *(float4*)&C.G[i_row][j0]     = make_float4(g0, g1, g2, g3);
            *(float4*)&C.G[i_row][j0 + 4] = make_float4(g4, g5, g6, g7);
            if (ct < DZ) {
                float acc = 0.f;
#pragma unroll
                for (int k0 = 0; k0 < DZ; k0 += 4) {
                    float4 a4 = *(const float4*)&C.A[ct][k0];
                    float4 m4 = *(const float4*)&C.mu[k0];
                    acc = fmaf(a4.x, m4.x, fmaf(a4.y, m4.y, fmaf(a4.z, m4.z, fmaf(a4.w, m4.w, acc))));
                }
#pragma unroll
                for (int k0 = 0; k0 < DU; k0 += 4) {
                    float4 b4 = *(const float4*)&C.Bt[ct][k0];
                    float4 u4 = *(const float4*)&C.u[k0];
                    acc = fmaf(b4.x, u4.x, fmaf(b4.y, u4.y, fmaf(b4.z, u4.z, fmaf(b4.w, u4.w, acc))));
                }
                C.mun[ct] = acc;
                out[OFF_MU + bt * 32u + (unsigned)ct] = acc;
            }
        }
        __syncthreads();

        // ===== stage C: S = G G^T + Q; store Sig from regs ====================
        {
            float s0=0.f,s1=0.f,s2=0.f,s3=0.f,s4=0.f,s5=0.f,s6=0.f,s7=0.f;
#pragma unroll
            for (int k0 = 0; k0 < DZ; k0 += 4) {
                float4 gi = *(const float4*)&C.G[i_row][k0];
#pragma unroll
                for (int r = 0; r < 8; ++r) {
                    float4 gr = *(const float4*)&C.G[j0 + r][k0];
                    float pv = fmaf(gi.x, gr.x, fmaf(gi.y, gr.y, fmaf(gi.z, gr.z, gi.w * gr.w)));
                    if      (r == 0) s0 += pv; else if (r == 1) s1 += pv;
                    else if (r == 2) s2 += pv; else if (r == 3) s3 += pv;
                    else if (r == 4) s4 += pv; else if (r == 5) s5 += pv;
                    else if (r == 6) s6 += pv; else               s7 += pv;
                }
            }
            float4 qlo = *(const float4*)&sh.Qm[i_row * 32 + j0];
            float4 qhi = *(const float4*)&sh.Qm[i_row * 32 + j0 + 4];
            float4 vlo = make_float4(s0+qlo.x, s1+qlo.y, s2+qlo.z, s3+qlo.w);
            float4 vhi = make_float4(s4+qhi.x, s5+qhi.y, s6+qhi.z, s7+qhi.w);
            *(float4*)&C.S[i_row][j0]     = vlo;
            *(float4*)&C.S[i_row][j0 + 4] = vhi;
            unsigned o = OFF_SIG + bt * 1024u + (unsigned)(i_row * 32 + j0);
            *(float4*)(out + o)     = vlo;
            *(float4*)(out + o + 4) = vhi;
        }
        __syncthreads();

        // ===== stage D: warp0 chol(+z); warps1-3 gh = h@Wh + bh ===============
        if (lw == 0) {
            chol32_warp(C, lane);
        } else {
            int g = ct - 32;                   // 0..95
            float acc0 = sh.bh[g], acc1 = sh.bh[g + 96];
#pragma unroll 8
            for (int hh = 0; hh < HID; ++hh) {
                float hv = C.h[hh];
                acc0 = fmaf(hv, sh.Wh[hh * G3 + g],      acc0);
                acc1 = fmaf(hv, sh.Wh[hh * G3 + g + 96], acc1);
            }
            C.gh[g] = acc0; C.gh[g + 96] = acc1;
        }
        __syncthreads();

        // ===== stage E: z/a_t out, mu roll; gx = z@Wx + bx ====================
        if (ct < 32) {
            out[OFF_Z + bt * 32u + (unsigned)ct] = C.z[ct];
            C.mu[ct] = C.mun[ct];
            if (ct < DA) {
                float acc = 0.f;
#pragma unroll
                for (int k0 = 0; k0 < DZ; k0 += 4) {
                    float4 c4 = *(const float4*)&C.Ct[ct][k0];
                    float4 z4 = *(const float4*)&C.z[k0];
                    acc = fmaf(c4.x, z4.x, fmaf(c4.y, z4.y, fmaf(c4.z, z4.z, fmaf(c4.w, z4.w, acc))));
                }
                out[OFF_A + bt * 16u + (unsigned)ct] = acc;
            }
        } else {
            int g = ct - 32;                   // 0..95
            float acc0 = sh.bx[g], acc1 = sh.bx[g + 96];
#pragma unroll 8
            for (int k = 0; k < DZ; ++k) {
                float zk = C.z[k];
                acc0 = fmaf(zk, sh.Wx[k * G3 + g],      acc0);
                acc1 = fmaf(zk, sh.Wx[k * G3 + g + 96], acc1);
            }
            C.gx[g] = acc0; C.gx[g + 96] = acc1;
        }
        __syncthreads();

        // ===== stage F (warp0 of chain): GRU + softmax -> alpha ===============
        if (lw == 0) {
            float p0 = 0.f, p1 = 0.f, p2 = 0.f, p3 = 0.f;
#pragma unroll
            for (int s = 0; s < 2; ++s) {
                int hh = lane + s * 32;
                float xr = C.gx[hh], xz = C.gx[64 + hh], xn = C.gx[128 + hh];
                float hr = C.gh[hh], hz = C.gh[64 + hh], hn = C.gh[128 + hh];
                float r  = fast_sigmoid(xr + hr);
                float zg = fast_sigmoid(xz + hz);
                float n  = fast_tanh(xn + r * hn);
                float hv = (1.f - zg) * n + zg * C.h[hh];
                C.h[hh] = hv;
                float4 w = *(const float4*)&sh.Wo[hh * 4];
                p0 = fmaf(hv, w.x, p0); p1 = fmaf(hv, w.y, p1);
                p2 = fmaf(hv, w.z, p2); p3 = fmaf(hv, w.w, p3);
            }
#pragma unroll
            for (int off = 16; off; off >>= 1) {
                p0 += __shfl_xor_sync(0xffffffffu, p0, off);
                p1 += __shfl_xor_sync(0xffffffffu, p1, off);
                p2 += __shfl_xor_sync(0xffffffffu, p2, off);
                p3 += __shfl_xor_sync(0xffffffffu, p3, off);
            }
            float o0 = p0 + sh.bo[0], o1 = p1 + sh.bo[1];
            float o2 = p2 + sh.bo[2], o3 = p3 + sh.bo[3];
            float m  = fmaxf(fmaxf(o0, o1), fmaxf(o2, o3));
            float e0 = __expf(o0 - m), e1 = __expf(o1 - m);
            float e2 = __expf(o2 - m), e3 = __expf(o3 - m);
            float s  = e0 + e1 + e2 + e3;
            if (lane == 0) {
                float inv = 1.f / s;
                C.alpha[0] = e0 * inv; C.alpha[1] = e1 * inv;
                C.alpha[2] = e2 * inv; C.alpha[3] = e3 * inv;
            }
        }
        __syncthreads();
    }
}

extern "C" void kernel_launch(void* const* d_in, const int* in_sizes, int n_in,
                              void* d_out, int out_size)
{
    size_t shbytes = sizeof(Shared);
    cudaFuncSetAttribute(lgssm_kernel,
                         cudaFuncAttributeMaxDynamicSharedMemorySize, (int)shbytes);
    lgssm_kernel<<<NBATCH / 2, NTHR, shbytes>>>(
        (const float*)d_in[0],  (const float*)d_in[1],  (const float*)d_in[2],
        (const float*)d_in[3],  (const float*)d_in[4],  (const float*)d_in[5],
        (const float*)d_in[6],  (const float*)d_in[7],  (const float*)d_in[8],
        (const float*)d_in[9],  (const float*)d_in[10], (const float*)d_in[11],
        (const float*)d_in[12], (const float*)d_in[13], (const float*)d_in[14],
        (const float*)d_in[15], (float*)d_out);
}